// round 3
// baseline (speedup 1.0000x reference)
#include <cuda_runtime.h>
#include <math.h>

// Problem shape (fixed by the dataset)
#define B_DIM 48
#define T_DIM 5000
#define F_DIM 161
#define BT (B_DIM * T_DIM)                  // 240000 rows
#define NEW_MAG_ELEMS ((size_t)BT * F_DIM)  // 38,640,000

#define CHUNK 200                  // frames per block (divides 5000, mult of 4)
#define CHUNKS_PB (T_DIM / CHUNK)  // 25 chunks per batch
#define NBLK (B_DIM * CHUNKS_PB)   // 1200 blocks
#define THREADS 512
#define CHUNK_ELEMS (CHUNK * F_DIM)  // 32200
#define CHUNK_F4 (CHUNK_ELEMS / 4)   // 8050 (exact)

// Scratch (no cudaMalloc): carry chain + ordering counter
__device__ float    g_carry[NBLK];
__device__ int      g_flag[NBLK];
__device__ unsigned g_counter;

__global__ void k_init() {
    int i = blockIdx.x * blockDim.x + threadIdx.x;
    if (i < NBLK) g_flag[i] = 0;
    if (i == 0) g_counter = 0u;
}

__global__ void __launch_bounds__(THREADS) k_fused(
    const float* __restrict__ mag,
    float* __restrict__ out,
    float* __restrict__ out_gain)
{
    __shared__ float sx[CHUNK];
    __shared__ float sA[CHUNK];
    __shared__ float sB[CHUNK];
    __shared__ float sinv[CHUNK];
    __shared__ unsigned s_vid;
    __shared__ float s_carry;

    int tid = threadIdx.x;
    if (tid == 0) s_vid = atomicAdd(&g_counter, 1u);
    __syncthreads();
    unsigned vid = s_vid;
    int b = vid % B_DIM;        // interleaved: all chunk-0 blocks first
    int c = vid / B_DIM;

    size_t row0 = (size_t)b * T_DIM + (size_t)c * CHUNK;
    const float* base = mag + row0 * F_DIM;

    // ---- pass 1: per-row one-sided power -> x (warp per row, DRAM read) ----
    int wid = tid >> 5, lane = tid & 31;
    for (int r = wid; r < CHUNK; r += THREADS / 32) {
        const float* m = base + (size_t)r * F_DIM;
        float s = 0.0f;
        #pragma unroll
        for (int f = lane; f < F_DIM; f += 32) {
            float v = m[f];
            s = fmaf(v, v, s);
        }
        #pragma unroll
        for (int off = 16; off > 0; off >>= 1)
            s += __shfl_xor_sync(0xffffffffu, s, off);
        if (lane == 0) {
            float m0 = m[0];
            float mN = m[F_DIM - 1];
            float sp = (2.0f * s - m0 * m0 - mN * mN) * (1.0f / 320.0f);
            sx[r] = sqrtf(sp);
        }
    }
    __syncthreads();

    // ---- warp 0: local affine-composition scan over CHUNK rows ----
    // g_t = A*g_{t-1} + B; (0.9, 0.1x) for t>=1; (0, x0) at t=0.
    if (wid == 0) {
        float cA = 1.0f, cB = 0.0f;
        int t_base = c * CHUNK;
        #pragma unroll
        for (int w = 0; w < (CHUNK + 31) / 32; w++) {
            int r = w * 32 + lane;
            float A, Bv;
            if (r < CHUNK) {
                float xv = sx[r];
                if (t_base + r == 0) { A = 0.0f; Bv = xv; }
                else                 { A = 0.9f; Bv = 0.1f * xv; }
            } else { A = 1.0f; Bv = 0.0f; }

            #pragma unroll
            for (int off = 1; off < 32; off <<= 1) {
                float Ap = __shfl_up_sync(0xffffffffu, A, off);
                float Bp = __shfl_up_sync(0xffffffffu, Bv, off);
                if (lane >= off) { Bv = fmaf(A, Bp, Bv); A *= Ap; }
            }
            float Apre = A * cA;               // compose with window carry
            float Bpre = fmaf(A, cB, Bv);
            if (r < CHUNK) { sA[r] = Apre; sB[r] = Bpre; }
            cA = __shfl_sync(0xffffffffu, Apre, 31);
            cB = __shfl_sync(0xffffffffu, Bpre, 31);
        }

        // ---- carry chain: wait for predecessor, publish after 1 FMA ----
        if (lane == 0) {
            float carry_in = 0.0f;
            if (c > 0) {
                int pidx = b * CHUNKS_PB + c - 1;
                while (atomicAdd(&g_flag[pidx], 0) == 0) {}
                __threadfence();
                carry_in = g_carry[pidx];
            }
            int idx = b * CHUNKS_PB + c;
            float carry_out = fmaf(sA[CHUNK - 1], carry_in, sB[CHUNK - 1]);
            g_carry[idx] = carry_out;
            __threadfence();
            atomicExch(&g_flag[idx], 1);
            s_carry = carry_in;
        }
    }
    __syncthreads();
    float carry = s_carry;

    // ---- gains + reciprocals, gain output ----
    float* og = out_gain + row0;
    for (int r = tid; r < CHUNK; r += THREADS) {
        float g = fmaf(sA[r], carry, sB[r]);
        og[r] = g;
        sinv[r] = 1.0f / (g + 0.001f);
    }
    __syncthreads();

    // ---- pass 2: new_mag = mag * inv (tile re-read hits L2), float4 ----
    const float4* m4 = (const float4*)base;
    float4* o4 = (float4*)(out + row0 * F_DIM);
    for (int i = tid; i < CHUNK_F4; i += THREADS) {
        float4 v = m4[i];
        int e = i * 4;
        float4 r;
        r.x = v.x * sinv[(e + 0) / F_DIM];
        r.y = v.y * sinv[(e + 1) / F_DIM];
        r.z = v.z * sinv[(e + 2) / F_DIM];
        r.w = v.w * sinv[(e + 3) / F_DIM];
        o4[i] = r;
    }
}

// ---------------------------------------------------------------------------
extern "C" void kernel_launch(void* const* d_in, const int* in_sizes, int n_in,
                              void* d_out, int out_size) {
    const float* mag = (const float*)d_in[0];
    float* out = (float*)d_out;
    float* out_gain = out + NEW_MAG_ELEMS;

    k_init<<<(NBLK + 255) / 256, 256>>>();
    k_fused<<<NBLK, THREADS>>>(mag, out, out_gain);
}